// round 2
// baseline (speedup 1.0000x reference)
#include <cuda_runtime.h>

#define NJ 24

__device__ __forceinline__ void axisang_rot(float x, float y, float z, float* __restrict__ R) {
    // matches reference: theta = sqrt(dot + 1e-8); R = I + s*K + (1-c)*K^2
    float t2 = x * x + y * y + z * z + 1e-8f;
    float th = sqrtf(t2);
    float inv = 1.0f / th;
    float ax = x * inv, ay = y * inv, az = z * inv;
    float s, c;
    sincosf(th, &s, &c);
    float oc = 1.0f - c;
    float xx = ax * ax, yy = ay * ay, zz = az * az;
    float xy = ax * ay, xz = ax * az, yz = ay * az;
    R[0] = 1.0f + oc * (-zz - yy);
    R[1] = -s * az + oc * xy;
    R[2] =  s * ay + oc * xz;
    R[3] =  s * az + oc * xy;
    R[4] = 1.0f + oc * (-zz - xx);
    R[5] = -s * ax + oc * yz;
    R[6] = -s * ay + oc * xz;
    R[7] =  s * ax + oc * yz;
    R[8] = 1.0f + oc * (-yy - xx);
}

// One joint: load bone axis-angle, emit rots/bone copies, chain l2w, emit l2w/kp/skts.
// P = parent 3x4 (row-major R[0..8], t[9..11]); C = output child 3x4.
__device__ __forceinline__ void do_joint(
    int j, int pj, bool is_root,
    size_t i, size_t idx,
    const float* __restrict__ bones, const float* __restrict__ rest,
    float px, float py, float pz,
    const float* __restrict__ P, float* __restrict__ C,
    float* __restrict__ kp, float* __restrict__ boneo,
    float* __restrict__ skts, float* __restrict__ l2w, float* __restrict__ rotso)
{
    // ---- bone load + copy-through ----
    size_t bofs = (idx * NJ + (size_t)j) * 3;
    float vx = __ldg(bones + bofs + 0);
    float vy = __ldg(bones + bofs + 1);
    float vz = __ldg(bones + bofs + 2);
    size_t o3 = (i * NJ + (size_t)j) * 3;
    boneo[o3 + 0] = vx; boneo[o3 + 1] = vy; boneo[o3 + 2] = vz;

    // ---- rotation ----
    float R[9];
    axisang_rot(vx, vy, vz, R);
    size_t o9 = (i * NJ + (size_t)j) * 9;
#pragma unroll
    for (int k = 0; k < 9; k++) rotso[o9 + k] = R[k];

    // ---- relative translation ----
    float tx, ty, tz;
    if (is_root) {
        tx = __ldg(rest + 0); ty = __ldg(rest + 1); tz = __ldg(rest + 2);
    } else {
        tx = __ldg(rest + 3 * j + 0) - __ldg(rest + 3 * pj + 0);
        ty = __ldg(rest + 3 * j + 1) - __ldg(rest + 3 * pj + 1);
        tz = __ldg(rest + 3 * j + 2) - __ldg(rest + 3 * pj + 2);
    }

    // ---- chain: C = P o [R|t] ----
    if (is_root) {
#pragma unroll
        for (int k = 0; k < 9; k++) C[k] = R[k];
        C[9] = tx; C[10] = ty; C[11] = tz;
    } else {
#pragma unroll
        for (int r = 0; r < 3; r++) {
#pragma unroll
            for (int cc = 0; cc < 3; cc++) {
                C[3 * r + cc] = P[3 * r + 0] * R[0 + cc]
                              + P[3 * r + 1] * R[3 + cc]
                              + P[3 * r + 2] * R[6 + cc];
            }
            C[9 + r] = P[3 * r + 0] * tx + P[3 * r + 1] * ty + P[3 * r + 2] * tz + P[9 + r];
        }
    }

    // ---- world translation (pelvis folded in) ----
    float twx = C[9] + px, twy = C[10] + py, twz = C[11] + pz;

    // ---- l2w write (4x float4, 64B aligned) ----
    size_t o16 = (i * NJ + (size_t)j) * 16;
    float4* l4 = reinterpret_cast<float4*>(l2w + o16);
    l4[0] = make_float4(C[0], C[1], C[2], twx);
    l4[1] = make_float4(C[3], C[4], C[5], twy);
    l4[2] = make_float4(C[6], C[7], C[8], twz);
    l4[3] = make_float4(0.0f, 0.0f, 0.0f, 1.0f);

    // ---- keypoint ----
    kp[o3 + 0] = twx; kp[o3 + 1] = twy; kp[o3 + 2] = twz;

    // ---- exact 3x3 inverse (adjugate) + rigid inverse translation ----
    float c00 = C[4] * C[8] - C[5] * C[7];
    float c01 = C[5] * C[6] - C[3] * C[8];
    float c02 = C[3] * C[7] - C[4] * C[6];
    float det = C[0] * c00 + C[1] * c01 + C[2] * c02;
    float id = 1.0f / det;
    float i00 = c00 * id;
    float i01 = (C[2] * C[7] - C[1] * C[8]) * id;
    float i02 = (C[1] * C[5] - C[2] * C[4]) * id;
    float i10 = c01 * id;
    float i11 = (C[0] * C[8] - C[2] * C[6]) * id;
    float i12 = (C[2] * C[3] - C[0] * C[5]) * id;
    float i20 = c02 * id;
    float i21 = (C[1] * C[6] - C[0] * C[7]) * id;
    float i22 = (C[0] * C[4] - C[1] * C[3]) * id;
    float itx = -(i00 * twx + i01 * twy + i02 * twz);
    float ity = -(i10 * twx + i11 * twy + i12 * twz);
    float itz = -(i20 * twx + i21 * twy + i22 * twz);
    float4* s4 = reinterpret_cast<float4*>(skts + o16);
    s4[0] = make_float4(i00, i01, i02, itx);
    s4[1] = make_float4(i10, i11, i12, ity);
    s4[2] = make_float4(i20, i21, i22, itz);
    s4[3] = make_float4(0.0f, 0.0f, 0.0f, 1.0f);
}

__global__ void __launch_bounds__(256)
kin_kernel(const float* __restrict__ pelvis, const float* __restrict__ bones,
           const float* __restrict__ rest, const int* __restrict__ idxs,
           float* __restrict__ out, int B)
{
    int ii = blockIdx.x * blockDim.x + threadIdx.x;
    if (ii >= B) return;
    size_t i = (size_t)ii;
    size_t idx = (size_t)idxs[i];

    float px = __ldg(pelvis + idx * 3 + 0);
    float py = __ldg(pelvis + idx * 3 + 1);
    float pz = __ldg(pelvis + idx * 3 + 2);

    size_t Bs = (size_t)B;
    float* kp    = out;               // B*24*3
    float* boneo = out + Bs * 72;     // B*24*3
    float* skts  = out + Bs * 144;    // B*24*16
    float* l2w   = out + Bs * 528;    // B*24*16
    float* rotso = out + Bs * 912;    // B*24*9

    float M0[12], M9[12], Ma[12], Mb[12];

#define J(j, pj, rt, PM, CM) \
    do_joint(j, pj, rt, i, idx, bones, rest, px, py, pz, PM, CM, kp, boneo, skts, l2w, rotso)

    // root
    J(0, 0, true, (const float*)nullptr, M0);
    // chain: 1 -> 4 -> 7 -> 10
    J(1, 0, false, M0, Ma); J(4, 1, false, Ma, Mb); J(7, 4, false, Mb, Ma); J(10, 7, false, Ma, Mb);
    // chain: 2 -> 5 -> 8 -> 11
    J(2, 0, false, M0, Ma); J(5, 2, false, Ma, Mb); J(8, 5, false, Mb, Ma); J(11, 8, false, Ma, Mb);
    // chain: 3 -> 6 -> 9 (keep M9: 3 children)
    J(3, 0, false, M0, Ma); J(6, 3, false, Ma, Mb); J(9, 6, false, Mb, M9);
    // 9 -> 12 -> 15
    J(12, 9, false, M9, Ma); J(15, 12, false, Ma, Mb);
    // 9 -> 13 -> 16 -> 18 -> 20 -> 22
    J(13, 9, false, M9, Ma); J(16, 13, false, Ma, Mb); J(18, 16, false, Mb, Ma);
    J(20, 18, false, Ma, Mb); J(22, 20, false, Mb, Ma);
    // 9 -> 14 -> 17 -> 19 -> 21 -> 23
    J(14, 9, false, M9, Ma); J(17, 14, false, Ma, Mb); J(19, 17, false, Mb, Ma);
    J(21, 19, false, Ma, Mb); J(23, 21, false, Mb, Ma);
#undef J
}

extern "C" void kernel_launch(void* const* d_in, const int* in_sizes, int n_in,
                              void* d_out, int out_size)
{
    const float* pelvis = (const float*)d_in[0];
    const float* bones  = (const float*)d_in[1];
    const float* rest   = (const float*)d_in[2];
    const int*   idxs   = (const int*)d_in[3];
    int B = in_sizes[3];

    int threads = 256;
    int blocks = (B + threads - 1) / threads;
    kin_kernel<<<blocks, threads>>>(pelvis, bones, rest, idxs, (float*)d_out, B);
}

// round 4
// speedup vs baseline: 2.8448x; 2.8448x over previous
#include <cuda_runtime.h>

#define FULLMASK 0xffffffffu

__device__ __forceinline__ void axisang_rot(float x, float y, float z, float* __restrict__ R) {
    // matches reference: theta = sqrt(dot + 1e-8); R = I + s*K + (1-c)*K^2
    float t2 = x * x + y * y + z * z + 1e-8f;
    float th = sqrtf(t2);
    float inv = 1.0f / th;
    float ax = x * inv, ay = y * inv, az = z * inv;
    float s, c;
    sincosf(th, &s, &c);
    float oc = 1.0f - c;
    float xx = ax * ax, yy = ay * ay, zz = az * az;
    float xy = ax * ay, xz = ax * az, yz = ay * az;
    R[0] = 1.0f + oc * (-zz - yy);
    R[1] = -s * az + oc * xy;
    R[2] =  s * ay + oc * xz;
    R[3] =  s * az + oc * xy;
    R[4] = 1.0f + oc * (-zz - xx);
    R[5] = -s * ax + oc * yz;
    R[6] = -s * ay + oc * xz;
    R[7] =  s * ax + oc * yz;
    R[8] = 1.0f + oc * (-yy - xx);
}

// ---------------------------------------------------------------------------
// Kernel 1: kinematic chain -> l2ws, skts, kp  (warp-staged coalesced stores)
// Per-warp smem (words): L[32*68] l2w stage | S[32*68] skts stage |
//                        BN[32*73] bones rows | KP[32*13] keypoints
// ---------------------------------------------------------------------------
#define WARP_WORDS (2176 + 2176 + 2336 + 416)  // 7104

__global__ void __launch_bounds__(128)
chain_kernel(const float* __restrict__ pelvis, const float* __restrict__ bones,
             const float* __restrict__ rest, const int* __restrict__ idxs,
             float* __restrict__ out, int B)
{
    extern __shared__ float sm[];
    const int lane = threadIdx.x & 31;
    const int wid  = threadIdx.x >> 5;
    float* Lb = sm + wid * WARP_WORDS;
    float* Sb = Lb + 2176;
    float* BN = Sb + 2176;
    float* KP = BN + 2336;

    const int i0 = blockIdx.x * 128 + wid * 32;
    const int i  = i0 + lane;
    const bool act = (i < B);
    const int myidx = act ? idxs[i] : 0;

    float px, py, pz;
    {
        size_t pb = (size_t)myidx * 3;
        px = __ldg(pelvis + pb + 0);
        py = __ldg(pelvis + pb + 1);
        pz = __ldg(pelvis + pb + 2);
    }

    // ---- coalesced bones pre-gather: 32 rows x 72 floats (smem stride 73) ----
#pragma unroll
    for (int it = 0; it < 18; ++it) {
        int q = it * 32 + lane;
        int r = q / 18;
        int f = q - r * 18;
        int ridx = __shfl_sync(FULLMASK, myidx, r);
        const float4 v = *reinterpret_cast<const float4*>(bones + (size_t)ridx * 72 + f * 4);
        float* d = BN + r * 73 + f * 4;
        d[0] = v.x; d[1] = v.y; d[2] = v.z; d[3] = v.w;
    }
    __syncwarp();

    const size_t Bs = (size_t)B;
    float* kpo   = out;                 // B*24*3
    float* sktso = out + Bs * 144;      // B*24*16
    float* l2wo  = out + Bs * 528;      // B*24*16

    float Ms[24][12];   // constant-indexed -> registers, liveness-pruned

#define JOINT(j, pj)                                                            \
    do {                                                                        \
        const float* bq = BN + lane * 73 + (j) * 3;                             \
        float R[9];                                                             \
        axisang_rot(bq[0], bq[1], bq[2], R);                                    \
        float tx, ty, tz;                                                       \
        if ((j) == 0) {                                                         \
            tx = __ldg(rest + 0); ty = __ldg(rest + 1); tz = __ldg(rest + 2);   \
        } else {                                                                \
            tx = __ldg(rest + 3 * (j) + 0) - __ldg(rest + 3 * (pj) + 0);        \
            ty = __ldg(rest + 3 * (j) + 1) - __ldg(rest + 3 * (pj) + 1);        \
            tz = __ldg(rest + 3 * (j) + 2) - __ldg(rest + 3 * (pj) + 2);        \
        }                                                                       \
        float* C = Ms[(j)];                                                     \
        if ((j) == 0) {                                                         \
            C[0]=R[0];C[1]=R[1];C[2]=R[2];C[3]=R[3];C[4]=R[4];C[5]=R[5];        \
            C[6]=R[6];C[7]=R[7];C[8]=R[8];C[9]=tx;C[10]=ty;C[11]=tz;            \
        } else {                                                                \
            const float* P = Ms[(pj)];                                          \
            _Pragma("unroll")                                                   \
            for (int r_ = 0; r_ < 3; r_++) {                                    \
                _Pragma("unroll")                                               \
                for (int c_ = 0; c_ < 3; c_++) {                                \
                    C[3*r_+c_] = P[3*r_+0]*R[0+c_] + P[3*r_+1]*R[3+c_]          \
                               + P[3*r_+2]*R[6+c_];                             \
                }                                                               \
                C[9+r_] = P[3*r_+0]*tx + P[3*r_+1]*ty + P[3*r_+2]*tz + P[9+r_]; \
            }                                                                   \
        }                                                                       \
        float twx = C[9] + px, twy = C[10] + py, twz = C[11] + pz;              \
        {   /* stage l2w (16B-aligned: lane*272B) */                            \
            float4* l4 = reinterpret_cast<float4*>(Lb + lane * 68 + ((j)&3)*16);\
            l4[0] = make_float4(C[0], C[1], C[2], twx);                         \
            l4[1] = make_float4(C[3], C[4], C[5], twy);                         \
            l4[2] = make_float4(C[6], C[7], C[8], twz);                         \
            l4[3] = make_float4(0.f, 0.f, 0.f, 1.f);                            \
        }                                                                       \
        {   /* stage kp */                                                      \
            float* kq = KP + lane * 13 + ((j)&3) * 3;                           \
            kq[0] = twx; kq[1] = twy; kq[2] = twz;                              \
        }                                                                       \
        {   /* exact adjugate inverse + rigid translation */                    \
            float c00 = C[4]*C[8] - C[5]*C[7];                                  \
            float c01 = C[5]*C[6] - C[3]*C[8];                                  \
            float c02 = C[3]*C[7] - C[4]*C[6];                                  \
            float det = C[0]*c00 + C[1]*c01 + C[2]*c02;                         \
            float id  = 1.0f / det;                                             \
            float i00 = c00*id, i01 = (C[2]*C[7]-C[1]*C[8])*id,                 \
                  i02 = (C[1]*C[5]-C[2]*C[4])*id;                               \
            float i10 = c01*id, i11 = (C[0]*C[8]-C[2]*C[6])*id,                 \
                  i12 = (C[2]*C[3]-C[0]*C[5])*id;                               \
            float i20 = c02*id, i21 = (C[1]*C[6]-C[0]*C[7])*id,                 \
                  i22 = (C[0]*C[4]-C[1]*C[3])*id;                               \
            float itx = -(i00*twx + i01*twy + i02*twz);                         \
            float ity = -(i10*twx + i11*twy + i12*twz);                         \
            float itz = -(i20*twx + i21*twy + i22*twz);                         \
            float4* s4 = reinterpret_cast<float4*>(Sb + lane * 68 + ((j)&3)*16);\
            s4[0] = make_float4(i00, i01, i02, itx);                            \
            s4[1] = make_float4(i10, i11, i12, ity);                            \
            s4[2] = make_float4(i20, i21, i22, itz);                            \
            s4[3] = make_float4(0.f, 0.f, 0.f, 1.f);                            \
        }                                                                       \
    } while (0)

#define FLUSH(c)                                                                \
    do {                                                                        \
        __syncwarp();                                                           \
        _Pragma("unroll")                                                       \
        for (int k = 0; k < 16; ++k) {                                          \
            int q = k * 32 + lane;                                              \
            int r = q >> 4;                                                     \
            int w = (q & 15) * 4;                                               \
            float4 a = *reinterpret_cast<float4*>(Lb + r * 68 + w);             \
            float4 b = *reinterpret_cast<float4*>(Sb + r * 68 + w);             \
            if (i0 + r < B) {                                                   \
                size_t base = (size_t)(i0 + r) * 384 + (c) * 64 + w;            \
                *reinterpret_cast<float4*>(l2wo + base)  = a;                   \
                *reinterpret_cast<float4*>(sktso + base) = b;                   \
            }                                                                   \
        }                                                                       \
        _Pragma("unroll")                                                       \
        for (int k = 0; k < 12; ++k) {                                          \
            int q = k * 32 + lane;                                              \
            int r = q / 12;                                                     \
            int m = q - r * 12;                                                 \
            if (i0 + r < B)                                                     \
                kpo[(size_t)(i0 + r) * 72 + (c) * 12 + m] = KP[r * 13 + m];     \
        }                                                                       \
        __syncwarp();                                                           \
    } while (0)

    // topological order: parent index always < joint index
    JOINT(0, 0);  JOINT(1, 0);  JOINT(2, 0);  JOINT(3, 0);   FLUSH(0);
    JOINT(4, 1);  JOINT(5, 2);  JOINT(6, 3);  JOINT(7, 4);   FLUSH(1);
    JOINT(8, 5);  JOINT(9, 6);  JOINT(10, 7); JOINT(11, 8);  FLUSH(2);
    JOINT(12, 9); JOINT(13, 9); JOINT(14, 9); JOINT(15, 12); FLUSH(3);
    JOINT(16, 13);JOINT(17, 14);JOINT(18, 16);JOINT(19, 17); FLUSH(4);
    JOINT(20, 18);JOINT(21, 19);JOINT(22, 20);JOINT(23, 21); FLUSH(5);

#undef JOINT
#undef FLUSH
}

// ---------------------------------------------------------------------------
// Kernel 2: rots + bone copy  (one thread per (element, joint) pair;
// outputs staged in smem, flushed fully coalesced)
// ---------------------------------------------------------------------------
__global__ void __launch_bounds__(256)
rot_kernel(const float* __restrict__ bones, const int* __restrict__ idxs,
           float* __restrict__ out, int B)
{
    __shared__ float rt[256 * 9];
    __shared__ float bt[256 * 3];
    const int tid = threadIdx.x;
    const long long p0 = (long long)blockIdx.x * 256;
    const long long p  = p0 + tid;
    const long long NP = (long long)B * 24;

    int ii = (int)(p / 24);
    int jj = (int)(p - (long long)ii * 24);
    const bool act = (p < NP);
    const int idx = act ? idxs[ii] : 0;

    const float* bp = bones + (size_t)idx * 72 + jj * 3;
    float vx = __ldg(bp + 0), vy = __ldg(bp + 1), vz = __ldg(bp + 2);
    bt[tid * 3 + 0] = vx; bt[tid * 3 + 1] = vy; bt[tid * 3 + 2] = vz;

    float R[9];
    axisang_rot(vx, vy, vz, R);
#pragma unroll
    for (int m = 0; m < 9; ++m) rt[tid * 9 + m] = R[m];

    __syncthreads();

    float* rotso = out + (size_t)B * 912;
    float* boneo = out + (size_t)B * 72;

    const long long rbase = p0 * 9;
#pragma unroll
    for (int k = 0; k < 3; ++k) {
        int q = k * 256 + tid;
        if (q < 576) {
            long long g = rbase + (long long)q * 4;
            if (g < (long long)B * 216)
                *reinterpret_cast<float4*>(rotso + g) =
                    reinterpret_cast<float4*>(rt)[q];
        }
    }
    if (tid < 192) {
        long long g = p0 * 3 + (long long)tid * 4;
        if (g < (long long)B * 72)
            *reinterpret_cast<float4*>(boneo + g) =
                reinterpret_cast<float4*>(bt)[tid];
    }
}

extern "C" void kernel_launch(void* const* d_in, const int* in_sizes, int n_in,
                              void* d_out, int out_size)
{
    const float* pelvis = (const float*)d_in[0];
    const float* bones  = (const float*)d_in[1];
    const float* rest   = (const float*)d_in[2];
    const int*   idxs   = (const int*)d_in[3];
    const int B = in_sizes[3];
    float* out = (float*)d_out;

    const int smem1 = 4 * WARP_WORDS * 4;  // 113,664 bytes
    cudaFuncSetAttribute(chain_kernel,
                         cudaFuncAttributeMaxDynamicSharedMemorySize, smem1);

    int blocks1 = (B + 127) / 128;
    chain_kernel<<<blocks1, 128, smem1>>>(pelvis, bones, rest, idxs, out, B);

    long long pairs = (long long)B * 24;
    int blocks2 = (int)((pairs + 255) / 256);
    rot_kernel<<<blocks2, 256>>>(bones, idxs, out, B);
}

// round 6
// speedup vs baseline: 4.2437x; 1.4917x over previous
#include <cuda_runtime.h>

#define FULLMASK 0xffffffffu

__device__ __forceinline__ void axisang_rot(float x, float y, float z, float* __restrict__ R) {
    // matches reference: theta = sqrt(dot + 1e-8); R = I + s*K + (1-c)*K^2
    float t2 = x * x + y * y + z * z + 1e-8f;
    float th = sqrtf(t2);
    float inv = 1.0f / th;
    float ax = x * inv, ay = y * inv, az = z * inv;
    float s, c;
    sincosf(th, &s, &c);
    float oc = 1.0f - c;
    float xx = ax * ax, yy = ay * ay, zz = az * az;
    float xy = ax * ay, xz = ax * az, yz = ay * az;
    R[0] = 1.0f + oc * (-zz - yy);
    R[1] = -s * az + oc * xy;
    R[2] =  s * ay + oc * xz;
    R[3] =  s * az + oc * xy;
    R[4] = 1.0f + oc * (-zz - xx);
    R[5] = -s * ax + oc * yz;
    R[6] = -s * ay + oc * xz;
    R[7] =  s * ax + oc * yz;
    R[8] = 1.0f + oc * (-yy - xx);
}

// ---------------------------------------------------------------------------
// Kernel 1: kinematic chain -> l2ws, skts, kp
// Per-warp smem (words): L[32*36] | S[32*36] | KP[32*7] = 2528 words (10.1 KB)
// Stage stride 36 words = 144 B (16B-aligned, conflict-free in quarter-warp
// float4 phases). Flush every 2 joints, fully coalesced float4 stores.
// Bones loaded per-thread in 4-joint chunks (3x LDG.128, registers).
// ---------------------------------------------------------------------------
#define LS_STRIDE 36
#define WARP_WORDS (1152 + 1152 + 224)  // 2528

__global__ void __launch_bounds__(128)
chain_kernel(const float* __restrict__ pelvis, const float* __restrict__ bones,
             const float* __restrict__ rest, const int* __restrict__ idxs,
             float* __restrict__ out, int B)
{
    extern __shared__ float sm[];
    const int lane = threadIdx.x & 31;
    const int wid  = threadIdx.x >> 5;
    float* Lb = sm + wid * WARP_WORDS;
    float* Sb = Lb + 1152;
    float* KP = Sb + 1152;

    const int i0 = blockIdx.x * 128 + wid * 32;
    const int i  = i0 + lane;
    const bool act = (i < B);
    const int myidx = act ? idxs[act ? i : 0] : 0;

    float px, py, pz;
    {
        size_t pb = (size_t)myidx * 3;
        px = __ldg(pelvis + pb + 0);
        py = __ldg(pelvis + pb + 1);
        pz = __ldg(pelvis + pb + 2);
    }

    const size_t Bs = (size_t)B;
    float* kpo   = out;                 // B*24*3
    float* sktso = out + Bs * 144;      // B*24*16
    float* l2wo  = out + Bs * 528;      // B*24*16

    float Ms[24][12];   // constant-indexed -> registers, liveness-pruned
    float bf[12];       // current 4-joint bone chunk

    // load a 4-joint bone chunk (48B, 16B-aligned) into bf
#define BONES4(j0)                                                              \
    do {                                                                        \
        const float4* bp = reinterpret_cast<const float4*>(                     \
            bones + (size_t)myidx * 72 + (j0) * 3);                             \
        float4 b0 = __ldg(bp + 0), b1 = __ldg(bp + 1), b2 = __ldg(bp + 2);      \
        bf[0]=b0.x; bf[1]=b0.y; bf[2]=b0.z; bf[3]=b0.w;                         \
        bf[4]=b1.x; bf[5]=b1.y; bf[6]=b1.z; bf[7]=b1.w;                         \
        bf[8]=b2.x; bf[9]=b2.y; bf[10]=b2.z; bf[11]=b2.w;                       \
    } while (0)

#define JOINT(j, pj)                                                            \
    do {                                                                        \
        float R[9];                                                             \
        axisang_rot(bf[((j)&3)*3+0], bf[((j)&3)*3+1], bf[((j)&3)*3+2], R);      \
        float tx, ty, tz;                                                       \
        if ((j) == 0) {                                                         \
            tx = __ldg(rest + 0); ty = __ldg(rest + 1); tz = __ldg(rest + 2);   \
        } else {                                                                \
            tx = __ldg(rest + 3 * (j) + 0) - __ldg(rest + 3 * (pj) + 0);        \
            ty = __ldg(rest + 3 * (j) + 1) - __ldg(rest + 3 * (pj) + 1);        \
            tz = __ldg(rest + 3 * (j) + 2) - __ldg(rest + 3 * (pj) + 2);        \
        }                                                                       \
        float* C = Ms[(j)];                                                     \
        if ((j) == 0) {                                                         \
            C[0]=R[0];C[1]=R[1];C[2]=R[2];C[3]=R[3];C[4]=R[4];C[5]=R[5];        \
            C[6]=R[6];C[7]=R[7];C[8]=R[8];C[9]=tx;C[10]=ty;C[11]=tz;            \
        } else {                                                                \
            const float* P = Ms[(pj)];                                          \
            _Pragma("unroll")                                                   \
            for (int r_ = 0; r_ < 3; r_++) {                                    \
                _Pragma("unroll")                                               \
                for (int c_ = 0; c_ < 3; c_++) {                                \
                    C[3*r_+c_] = P[3*r_+0]*R[0+c_] + P[3*r_+1]*R[3+c_]          \
                               + P[3*r_+2]*R[6+c_];                             \
                }                                                               \
                C[9+r_] = P[3*r_+0]*tx + P[3*r_+1]*ty + P[3*r_+2]*tz + P[9+r_]; \
            }                                                                   \
        }                                                                       \
        float twx = C[9] + px, twy = C[10] + py, twz = C[11] + pz;              \
        {   /* stage l2w (stride 144B -> 16B-aligned) */                        \
            float4* l4 = reinterpret_cast<float4*>(                             \
                Lb + lane * LS_STRIDE + ((j)&1)*16);                            \
            l4[0] = make_float4(C[0], C[1], C[2], twx);                         \
            l4[1] = make_float4(C[3], C[4], C[5], twy);                         \
            l4[2] = make_float4(C[6], C[7], C[8], twz);                         \
            l4[3] = make_float4(0.f, 0.f, 0.f, 1.f);                            \
        }                                                                       \
        {   /* stage kp */                                                      \
            float* kq = KP + lane * 7 + ((j)&1) * 3;                            \
            kq[0] = twx; kq[1] = twy; kq[2] = twz;                              \
        }                                                                       \
        {   /* exact adjugate inverse + rigid translation */                    \
            float c00 = C[4]*C[8] - C[5]*C[7];                                  \
            float c01 = C[5]*C[6] - C[3]*C[8];                                  \
            float c02 = C[3]*C[7] - C[4]*C[6];                                  \
            float det = C[0]*c00 + C[1]*c01 + C[2]*c02;                         \
            float id  = 1.0f / det;                                             \
            float i00 = c00*id, i01 = (C[2]*C[7]-C[1]*C[8])*id,                 \
                  i02 = (C[1]*C[5]-C[2]*C[4])*id;                               \
            float i10 = c01*id, i11 = (C[0]*C[8]-C[2]*C[6])*id,                 \
                  i12 = (C[2]*C[3]-C[0]*C[5])*id;                               \
            float i20 = c02*id, i21 = (C[1]*C[6]-C[0]*C[7])*id,                 \
                  i22 = (C[0]*C[4]-C[1]*C[3])*id;                               \
            float itx = -(i00*twx + i01*twy + i02*twz);                         \
            float ity = -(i10*twx + i11*twy + i12*twz);                         \
            float itz = -(i20*twx + i21*twy + i22*twz);                         \
            float4* s4 = reinterpret_cast<float4*>(                             \
                Sb + lane * LS_STRIDE + ((j)&1)*16);                            \
            s4[0] = make_float4(i00, i01, i02, itx);                            \
            s4[1] = make_float4(i10, i11, i12, ity);                            \
            s4[2] = make_float4(i20, i21, i22, itz);                            \
            s4[3] = make_float4(0.f, 0.f, 0.f, 1.f);                            \
        }                                                                       \
    } while (0)

    // flush 2 staged joints (chunk c = 0..11): 32 floats/elem -> 8 float4 iters
#define FLUSH(c)                                                                \
    do {                                                                        \
        __syncwarp();                                                           \
        _Pragma("unroll")                                                       \
        for (int k = 0; k < 8; ++k) {                                           \
            int q = k * 32 + lane;                                              \
            int r = q >> 3;                                                     \
            int w = (q & 7) * 4;                                                \
            float4 a = *reinterpret_cast<float4*>(Lb + r * LS_STRIDE + w);      \
            float4 b = *reinterpret_cast<float4*>(Sb + r * LS_STRIDE + w);      \
            if (i0 + r < B) {                                                   \
                size_t base = (size_t)(i0 + r) * 384 + (c) * 32 + w;            \
                *reinterpret_cast<float4*>(l2wo + base)  = a;                   \
                *reinterpret_cast<float4*>(sktso + base) = b;                   \
            }                                                                   \
        }                                                                       \
        _Pragma("unroll")                                                       \
        for (int k = 0; k < 6; ++k) {                                           \
            int q = k * 32 + lane;                                              \
            int r = q / 6;                                                      \
            int m = q - r * 6;                                                  \
            if (i0 + r < B)                                                     \
                kpo[(size_t)(i0 + r) * 72 + (c) * 6 + m] = KP[r * 7 + m];       \
        }                                                                       \
        __syncwarp();                                                           \
    } while (0)

    // topological order; parent always computed before child
    BONES4(0);
    JOINT(0, 0);   JOINT(1, 0);   FLUSH(0);
    JOINT(2, 0);   JOINT(3, 0);   FLUSH(1);
    BONES4(4);
    JOINT(4, 1);   JOINT(5, 2);   FLUSH(2);
    JOINT(6, 3);   JOINT(7, 4);   FLUSH(3);
    BONES4(8);
    JOINT(8, 5);   JOINT(9, 6);   FLUSH(4);
    JOINT(10, 7);  JOINT(11, 8);  FLUSH(5);
    BONES4(12);
    JOINT(12, 9);  JOINT(13, 9);  FLUSH(6);
    JOINT(14, 9);  JOINT(15, 12); FLUSH(7);
    BONES4(16);
    JOINT(16, 13); JOINT(17, 14); FLUSH(8);
    JOINT(18, 16); JOINT(19, 17); FLUSH(9);
    BONES4(20);
    JOINT(20, 18); JOINT(21, 19); FLUSH(10);
    JOINT(22, 20); JOINT(23, 21); FLUSH(11);

#undef JOINT
#undef FLUSH
#undef BONES4
}

// ---------------------------------------------------------------------------
// Kernel 2: rots + bone copy  (one thread per (element, joint) pair;
// outputs staged in smem, flushed fully coalesced)
// ---------------------------------------------------------------------------
__global__ void __launch_bounds__(256)
rot_kernel(const float* __restrict__ bones, const int* __restrict__ idxs,
           float* __restrict__ out, int B)
{
    __shared__ float rt[256 * 9];
    __shared__ float bt[256 * 3];
    const int tid = threadIdx.x;
    const long long p0 = (long long)blockIdx.x * 256;
    const long long p  = p0 + tid;
    const long long NP = (long long)B * 24;

    int ii = (int)(p / 24);
    int jj = (int)(p - (long long)ii * 24);
    const bool act = (p < NP);
    const int idx = act ? idxs[ii] : 0;

    const float* bp = bones + (size_t)idx * 72 + jj * 3;
    float vx = __ldg(bp + 0), vy = __ldg(bp + 1), vz = __ldg(bp + 2);
    bt[tid * 3 + 0] = vx; bt[tid * 3 + 1] = vy; bt[tid * 3 + 2] = vz;

    float R[9];
    axisang_rot(vx, vy, vz, R);
#pragma unroll
    for (int m = 0; m < 9; ++m) rt[tid * 9 + m] = R[m];

    __syncthreads();

    float* rotso = out + (size_t)B * 912;
    float* boneo = out + (size_t)B * 72;

    const long long rbase = p0 * 9;
#pragma unroll
    for (int k = 0; k < 3; ++k) {
        int q = k * 256 + tid;
        if (q < 576) {
            long long g = rbase + (long long)q * 4;
            if (g < (long long)B * 216)
                *reinterpret_cast<float4*>(rotso + g) =
                    reinterpret_cast<float4*>(rt)[q];
        }
    }
    if (tid < 192) {
        long long g = p0 * 3 + (long long)tid * 4;
        if (g < (long long)B * 72)
            *reinterpret_cast<float4*>(boneo + g) =
                reinterpret_cast<float4*>(bt)[tid];
    }
}

extern "C" void kernel_launch(void* const* d_in, const int* in_sizes, int n_in,
                              void* d_out, int out_size)
{
    const float* pelvis = (const float*)d_in[0];
    const float* bones  = (const float*)d_in[1];
    const float* rest   = (const float*)d_in[2];
    const int*   idxs   = (const int*)d_in[3];
    const int B = in_sizes[3];
    float* out = (float*)d_out;

    const int smem1 = 4 * WARP_WORDS * 4;  // 40,448 bytes
    cudaFuncSetAttribute(chain_kernel,
                         cudaFuncAttributeMaxDynamicSharedMemorySize, smem1);

    int blocks1 = (B + 127) / 128;
    chain_kernel<<<blocks1, 128, smem1>>>(pelvis, bones, rest, idxs, out, B);

    long long pairs = (long long)B * 24;
    int blocks2 = (int)((pairs + 255) / 256);
    rot_kernel<<<blocks2, 256>>>(bones, idxs, out, B);
}

// round 7
// speedup vs baseline: 5.7664x; 1.3588x over previous
#include <cuda_runtime.h>

#define FULLMASK 0xffffffffu

__device__ __forceinline__ void axisang_rot(float x, float y, float z, float* __restrict__ R) {
    // reference: theta = sqrt(dot + 1e-8); R = I + s*K + (1-c)*K^2
    // fast-math version: MUFU.RSQ / MUFU.SIN / MUFU.COS (error ~2^-21, budget 1e-3)
    float t2 = x * x + y * y + z * z + 1e-8f;
    float inv = rsqrtf(t2);
    float th = t2 * inv;            // sqrt(t2)
    float ax = x * inv, ay = y * inv, az = z * inv;
    float s = __sinf(th);
    float c = __cosf(th);
    float oc = 1.0f - c;
    float xx = ax * ax, yy = ay * ay, zz = az * az;
    float xy = ax * ay, xz = ax * az, yz = ay * az;
    R[0] = 1.0f + oc * (-zz - yy);
    R[1] = -s * az + oc * xy;
    R[2] =  s * ay + oc * xz;
    R[3] =  s * az + oc * xy;
    R[4] = 1.0f + oc * (-zz - xx);
    R[5] = -s * ax + oc * yz;
    R[6] = -s * ay + oc * xz;
    R[7] =  s * ax + oc * yz;
    R[8] = 1.0f + oc * (-yy - xx);
}

// ---------------------------------------------------------------------------
// Kernel 1: kinematic chain -> l2ws, skts, kp
// Per-warp smem (words): L[32*36] | S[32*36] | KP[32*7] = 2528 words (10.1 KB)
// Stage stride 36 words = 144 B (16B-aligned, conflict-free in quarter-warp
// float4 phases). Flush every 2 joints, fully coalesced float4 stores.
// Bones loaded per-thread in 4-joint chunks (3x LDG.128, registers).
// ---------------------------------------------------------------------------
#define LS_STRIDE 36
#define WARP_WORDS (1152 + 1152 + 224)  // 2528

__global__ void __launch_bounds__(128)
chain_kernel(const float* __restrict__ pelvis, const float* __restrict__ bones,
             const float* __restrict__ rest, const int* __restrict__ idxs,
             float* __restrict__ out, int B)
{
    extern __shared__ float sm[];
    const int lane = threadIdx.x & 31;
    const int wid  = threadIdx.x >> 5;
    float* Lb = sm + wid * WARP_WORDS;
    float* Sb = Lb + 1152;
    float* KP = Sb + 1152;

    const int i0 = blockIdx.x * 128 + wid * 32;
    const int i  = i0 + lane;
    const bool act = (i < B);
    const int myidx = act ? idxs[act ? i : 0] : 0;

    float px, py, pz;
    {
        size_t pb = (size_t)myidx * 3;
        px = __ldg(pelvis + pb + 0);
        py = __ldg(pelvis + pb + 1);
        pz = __ldg(pelvis + pb + 2);
    }

    const size_t Bs = (size_t)B;
    float* kpo   = out;                 // B*24*3
    float* sktso = out + Bs * 144;      // B*24*16
    float* l2wo  = out + Bs * 528;      // B*24*16

    float Ms[24][12];   // constant-indexed -> registers, liveness-pruned
    float bf[12];       // current 4-joint bone chunk

    // load a 4-joint bone chunk (48B, 16B-aligned) into bf
#define BONES4(j0)                                                              \
    do {                                                                        \
        const float4* bp = reinterpret_cast<const float4*>(                     \
            bones + (size_t)myidx * 72 + (j0) * 3);                             \
        float4 b0 = __ldg(bp + 0), b1 = __ldg(bp + 1), b2 = __ldg(bp + 2);      \
        bf[0]=b0.x; bf[1]=b0.y; bf[2]=b0.z; bf[3]=b0.w;                         \
        bf[4]=b1.x; bf[5]=b1.y; bf[6]=b1.z; bf[7]=b1.w;                         \
        bf[8]=b2.x; bf[9]=b2.y; bf[10]=b2.z; bf[11]=b2.w;                       \
    } while (0)

#define JOINT(j, pj)                                                            \
    do {                                                                        \
        float R[9];                                                             \
        axisang_rot(bf[((j)&3)*3+0], bf[((j)&3)*3+1], bf[((j)&3)*3+2], R);      \
        float tx, ty, tz;                                                       \
        if ((j) == 0) {                                                         \
            tx = __ldg(rest + 0); ty = __ldg(rest + 1); tz = __ldg(rest + 2);   \
        } else {                                                                \
            tx = __ldg(rest + 3 * (j) + 0) - __ldg(rest + 3 * (pj) + 0);        \
            ty = __ldg(rest + 3 * (j) + 1) - __ldg(rest + 3 * (pj) + 1);        \
            tz = __ldg(rest + 3 * (j) + 2) - __ldg(rest + 3 * (pj) + 2);        \
        }                                                                       \
        float* C = Ms[(j)];                                                     \
        if ((j) == 0) {                                                         \
            C[0]=R[0];C[1]=R[1];C[2]=R[2];C[3]=R[3];C[4]=R[4];C[5]=R[5];        \
            C[6]=R[6];C[7]=R[7];C[8]=R[8];C[9]=tx;C[10]=ty;C[11]=tz;            \
        } else {                                                                \
            const float* P = Ms[(pj)];                                          \
            _Pragma("unroll")                                                   \
            for (int r_ = 0; r_ < 3; r_++) {                                    \
                _Pragma("unroll")                                               \
                for (int c_ = 0; c_ < 3; c_++) {                                \
                    C[3*r_+c_] = P[3*r_+0]*R[0+c_] + P[3*r_+1]*R[3+c_]          \
                               + P[3*r_+2]*R[6+c_];                             \
                }                                                               \
                C[9+r_] = P[3*r_+0]*tx + P[3*r_+1]*ty + P[3*r_+2]*tz + P[9+r_]; \
            }                                                                   \
        }                                                                       \
        float twx = C[9] + px, twy = C[10] + py, twz = C[11] + pz;              \
        {   /* stage l2w (stride 144B -> 16B-aligned) */                        \
            float4* l4 = reinterpret_cast<float4*>(                             \
                Lb + lane * LS_STRIDE + ((j)&1)*16);                            \
            l4[0] = make_float4(C[0], C[1], C[2], twx);                         \
            l4[1] = make_float4(C[3], C[4], C[5], twy);                         \
            l4[2] = make_float4(C[6], C[7], C[8], twz);                         \
            l4[3] = make_float4(0.f, 0.f, 0.f, 1.f);                            \
        }                                                                       \
        {   /* stage kp */                                                      \
            float* kq = KP + lane * 7 + ((j)&1) * 3;                            \
            kq[0] = twx; kq[1] = twy; kq[2] = twz;                              \
        }                                                                       \
        {   /* exact adjugate inverse + rigid translation */                    \
            float c00 = C[4]*C[8] - C[5]*C[7];                                  \
            float c01 = C[5]*C[6] - C[3]*C[8];                                  \
            float c02 = C[3]*C[7] - C[4]*C[6];                                  \
            float det = C[0]*c00 + C[1]*c01 + C[2]*c02;                         \
            float id  = __fdividef(1.0f, det);                                  \
            float i00 = c00*id, i01 = (C[2]*C[7]-C[1]*C[8])*id,                 \
                  i02 = (C[1]*C[5]-C[2]*C[4])*id;                               \
            float i10 = c01*id, i11 = (C[0]*C[8]-C[2]*C[6])*id,                 \
                  i12 = (C[2]*C[3]-C[0]*C[5])*id;                               \
            float i20 = c02*id, i21 = (C[1]*C[6]-C[0]*C[7])*id,                 \
                  i22 = (C[0]*C[4]-C[1]*C[3])*id;                               \
            float itx = -(i00*twx + i01*twy + i02*twz);                         \
            float ity = -(i10*twx + i11*twy + i12*twz);                         \
            float itz = -(i20*twx + i21*twy + i22*twz);                         \
            float4* s4 = reinterpret_cast<float4*>(                             \
                Sb + lane * LS_STRIDE + ((j)&1)*16);                            \
            s4[0] = make_float4(i00, i01, i02, itx);                            \
            s4[1] = make_float4(i10, i11, i12, ity);                            \
            s4[2] = make_float4(i20, i21, i22, itz);                            \
            s4[3] = make_float4(0.f, 0.f, 0.f, 1.f);                            \
        }                                                                       \
    } while (0)

    // flush 2 staged joints (chunk c = 0..11): 32 floats/elem -> 8 float4 iters
#define FLUSH(c)                                                                \
    do {                                                                        \
        __syncwarp();                                                           \
        _Pragma("unroll")                                                       \
        for (int k = 0; k < 8; ++k) {                                           \
            int q = k * 32 + lane;                                              \
            int r = q >> 3;                                                     \
            int w = (q & 7) * 4;                                                \
            float4 a = *reinterpret_cast<float4*>(Lb + r * LS_STRIDE + w);      \
            float4 b = *reinterpret_cast<float4*>(Sb + r * LS_STRIDE + w);      \
            if (i0 + r < B) {                                                   \
                size_t base = (size_t)(i0 + r) * 384 + (c) * 32 + w;            \
                *reinterpret_cast<float4*>(l2wo + base)  = a;                   \
                *reinterpret_cast<float4*>(sktso + base) = b;                   \
            }                                                                   \
        }                                                                       \
        _Pragma("unroll")                                                       \
        for (int k = 0; k < 6; ++k) {                                           \
            int q = k * 32 + lane;                                              \
            int r = q / 6;                                                      \
            int m = q - r * 6;                                                  \
            if (i0 + r < B)                                                     \
                kpo[(size_t)(i0 + r) * 72 + (c) * 6 + m] = KP[r * 7 + m];       \
        }                                                                       \
        __syncwarp();                                                           \
    } while (0)

    // topological order; parent always computed before child
    BONES4(0);
    JOINT(0, 0);   JOINT(1, 0);   FLUSH(0);
    JOINT(2, 0);   JOINT(3, 0);   FLUSH(1);
    BONES4(4);
    JOINT(4, 1);   JOINT(5, 2);   FLUSH(2);
    JOINT(6, 3);   JOINT(7, 4);   FLUSH(3);
    BONES4(8);
    JOINT(8, 5);   JOINT(9, 6);   FLUSH(4);
    JOINT(10, 7);  JOINT(11, 8);  FLUSH(5);
    BONES4(12);
    JOINT(12, 9);  JOINT(13, 9);  FLUSH(6);
    JOINT(14, 9);  JOINT(15, 12); FLUSH(7);
    BONES4(16);
    JOINT(16, 13); JOINT(17, 14); FLUSH(8);
    JOINT(18, 16); JOINT(19, 17); FLUSH(9);
    BONES4(20);
    JOINT(20, 18); JOINT(21, 19); FLUSH(10);
    JOINT(22, 20); JOINT(23, 21); FLUSH(11);

#undef JOINT
#undef FLUSH
#undef BONES4
}

// ---------------------------------------------------------------------------
// Kernel 2: rots + bone copy  (one thread per (element, joint) pair;
// outputs staged in smem, flushed fully coalesced)
// ---------------------------------------------------------------------------
__global__ void __launch_bounds__(256)
rot_kernel(const float* __restrict__ bones, const int* __restrict__ idxs,
           float* __restrict__ out, int B)
{
    __shared__ float rt[256 * 9];
    __shared__ float bt[256 * 3];
    const int tid = threadIdx.x;
    const long long p0 = (long long)blockIdx.x * 256;
    const long long p  = p0 + tid;
    const long long NP = (long long)B * 24;

    int ii = (int)(p / 24);
    int jj = (int)(p - (long long)ii * 24);
    const bool act = (p < NP);
    const int idx = act ? idxs[ii] : 0;

    const float* bp = bones + (size_t)idx * 72 + jj * 3;
    float vx = __ldg(bp + 0), vy = __ldg(bp + 1), vz = __ldg(bp + 2);
    bt[tid * 3 + 0] = vx; bt[tid * 3 + 1] = vy; bt[tid * 3 + 2] = vz;

    float R[9];
    axisang_rot(vx, vy, vz, R);
#pragma unroll
    for (int m = 0; m < 9; ++m) rt[tid * 9 + m] = R[m];

    __syncthreads();

    float* rotso = out + (size_t)B * 912;
    float* boneo = out + (size_t)B * 72;

    const long long rbase = p0 * 9;
#pragma unroll
    for (int k = 0; k < 3; ++k) {
        int q = k * 256 + tid;
        if (q < 576) {
            long long g = rbase + (long long)q * 4;
            if (g < (long long)B * 216)
                *reinterpret_cast<float4*>(rotso + g) =
                    reinterpret_cast<float4*>(rt)[q];
        }
    }
    if (tid < 192) {
        long long g = p0 * 3 + (long long)tid * 4;
        if (g < (long long)B * 72)
            *reinterpret_cast<float4*>(boneo + g) =
                reinterpret_cast<float4*>(bt)[tid];
    }
}

extern "C" void kernel_launch(void* const* d_in, const int* in_sizes, int n_in,
                              void* d_out, int out_size)
{
    const float* pelvis = (const float*)d_in[0];
    const float* bones  = (const float*)d_in[1];
    const float* rest   = (const float*)d_in[2];
    const int*   idxs   = (const int*)d_in[3];
    const int B = in_sizes[3];
    float* out = (float*)d_out;

    const int smem1 = 4 * WARP_WORDS * 4;  // 40,448 bytes
    cudaFuncSetAttribute(chain_kernel,
                         cudaFuncAttributeMaxDynamicSharedMemorySize, smem1);

    int blocks1 = (B + 127) / 128;
    chain_kernel<<<blocks1, 128, smem1>>>(pelvis, bones, rest, idxs, out, B);

    long long pairs = (long long)B * 24;
    int blocks2 = (int)((pairs + 255) / 256);
    rot_kernel<<<blocks2, 256>>>(bones, idxs, out, B);
}

// round 10
// speedup vs baseline: 5.8477x; 1.0141x over previous
#include <cuda_runtime.h>

#define FULLMASK 0xffffffffu

__device__ __forceinline__ void axisang_rot(float x, float y, float z, float* __restrict__ R) {
    // reference: theta = sqrt(dot + 1e-8); R = I + s*K + (1-c)*K^2
    // fast-math version: MUFU.RSQ / MUFU.SIN / MUFU.COS (error ~2^-21, budget 1e-3)
    float t2 = x * x + y * y + z * z + 1e-8f;
    float inv = rsqrtf(t2);
    float th = t2 * inv;            // sqrt(t2)
    float ax = x * inv, ay = y * inv, az = z * inv;
    float s = __sinf(th);
    float c = __cosf(th);
    float oc = 1.0f - c;
    float xx = ax * ax, yy = ay * ay, zz = az * az;
    float xy = ax * ay, xz = ax * az, yz = ay * az;
    R[0] = 1.0f + oc * (-zz - yy);
    R[1] = -s * az + oc * xy;
    R[2] =  s * ay + oc * xz;
    R[3] =  s * az + oc * xy;
    R[4] = 1.0f + oc * (-zz - xx);
    R[5] = -s * ax + oc * yz;
    R[6] = -s * ay + oc * xz;
    R[7] =  s * ax + oc * yz;
    R[8] = 1.0f + oc * (-yy - xx);
}

// ---------------------------------------------------------------------------
// Kernel 1: kinematic chain -> l2ws, skts, kp
// Per-warp smem (words): L[32*36] | S[32*36] | KP[32*7] = 2528 words (10.1 KB)
// Stage stride 36 words = 144 B (16B-aligned, conflict-free in quarter-warp
// float4 phases). Flush every 2 joints, fully coalesced float4 stores.
// Bones loaded per-thread in 4-joint chunks (3x LDG.128, registers).
// Rigid inverse = [R^T | -R^T t]  (rotation chain => orthogonal, ~1e-5 vs LU).
// ---------------------------------------------------------------------------
#define LS_STRIDE 36
#define WARP_WORDS (1152 + 1152 + 224)  // 2528

__global__ void __launch_bounds__(128)
chain_kernel(const float* __restrict__ pelvis, const float* __restrict__ bones,
             const float* __restrict__ rest, const int* __restrict__ idxs,
             float* __restrict__ out, int B)
{
    extern __shared__ float sm[];
    const int lane = threadIdx.x & 31;
    const int wid  = threadIdx.x >> 5;
    float* Lb = sm + wid * WARP_WORDS;
    float* Sb = Lb + 1152;
    float* KP = Sb + 1152;

    const int i0 = blockIdx.x * 128 + wid * 32;
    const int i  = i0 + lane;
    const bool act = (i < B);
    const int myidx = act ? idxs[act ? i : 0] : 0;

    float px, py, pz;
    {
        size_t pb = (size_t)myidx * 3;
        px = __ldg(pelvis + pb + 0);
        py = __ldg(pelvis + pb + 1);
        pz = __ldg(pelvis + pb + 2);
    }

    const size_t Bs = (size_t)B;
    float* kpo   = out;                 // B*24*3
    float* sktso = out + Bs * 144;      // B*24*16
    float* l2wo  = out + Bs * 528;      // B*24*16

    float Ms[24][12];   // constant-indexed -> registers, liveness-pruned
    float bf[12];       // current 4-joint bone chunk

    // load a 4-joint bone chunk (48B, 16B-aligned) into bf
#define BONES4(j0)                                                              \
    do {                                                                        \
        const float4* bp = reinterpret_cast<const float4*>(                     \
            bones + (size_t)myidx * 72 + (j0) * 3);                             \
        float4 b0 = __ldg(bp + 0), b1 = __ldg(bp + 1), b2 = __ldg(bp + 2);      \
        bf[0]=b0.x; bf[1]=b0.y; bf[2]=b0.z; bf[3]=b0.w;                         \
        bf[4]=b1.x; bf[5]=b1.y; bf[6]=b1.z; bf[7]=b1.w;                         \
        bf[8]=b2.x; bf[9]=b2.y; bf[10]=b2.z; bf[11]=b2.w;                       \
    } while (0)

#define JOINT(j, pj)                                                            \
    do {                                                                        \
        float R[9];                                                             \
        axisang_rot(bf[((j)&3)*3+0], bf[((j)&3)*3+1], bf[((j)&3)*3+2], R);      \
        float tx, ty, tz;                                                       \
        if ((j) == 0) {                                                         \
            tx = __ldg(rest + 0); ty = __ldg(rest + 1); tz = __ldg(rest + 2);   \
        } else {                                                                \
            tx = __ldg(rest + 3 * (j) + 0) - __ldg(rest + 3 * (pj) + 0);        \
            ty = __ldg(rest + 3 * (j) + 1) - __ldg(rest + 3 * (pj) + 1);        \
            tz = __ldg(rest + 3 * (j) + 2) - __ldg(rest + 3 * (pj) + 2);        \
        }                                                                       \
        float* C = Ms[(j)];                                                     \
        if ((j) == 0) {                                                         \
            C[0]=R[0];C[1]=R[1];C[2]=R[2];C[3]=R[3];C[4]=R[4];C[5]=R[5];        \
            C[6]=R[6];C[7]=R[7];C[8]=R[8];C[9]=tx;C[10]=ty;C[11]=tz;            \
        } else {                                                                \
            const float* P = Ms[(pj)];                                          \
            _Pragma("unroll")                                                   \
            for (int r_ = 0; r_ < 3; r_++) {                                    \
                _Pragma("unroll")                                               \
                for (int c_ = 0; c_ < 3; c_++) {                                \
                    C[3*r_+c_] = P[3*r_+0]*R[0+c_] + P[3*r_+1]*R[3+c_]          \
                               + P[3*r_+2]*R[6+c_];                             \
                }                                                               \
                C[9+r_] = P[3*r_+0]*tx + P[3*r_+1]*ty + P[3*r_+2]*tz + P[9+r_]; \
            }                                                                   \
        }                                                                       \
        float twx = C[9] + px, twy = C[10] + py, twz = C[11] + pz;              \
        {   /* stage l2w (stride 144B -> 16B-aligned) */                        \
            float4* l4 = reinterpret_cast<float4*>(                             \
                Lb + lane * LS_STRIDE + ((j)&1)*16);                            \
            l4[0] = make_float4(C[0], C[1], C[2], twx);                         \
            l4[1] = make_float4(C[3], C[4], C[5], twy);                         \
            l4[2] = make_float4(C[6], C[7], C[8], twz);                         \
            l4[3] = make_float4(0.f, 0.f, 0.f, 1.f);                            \
        }                                                                       \
        {   /* stage kp */                                                      \
            float* kq = KP + lane * 7 + ((j)&1) * 3;                            \
            kq[0] = twx; kq[1] = twy; kq[2] = twz;                              \
        }                                                                       \
        {   /* rigid inverse: R^T and -R^T t (orthogonal rotation chain) */     \
            float itx = -(C[0]*twx + C[3]*twy + C[6]*twz);                      \
            float ity = -(C[1]*twx + C[4]*twy + C[7]*twz);                      \
            float itz = -(C[2]*twx + C[5]*twy + C[8]*twz);                      \
            float4* s4 = reinterpret_cast<float4*>(                             \
                Sb + lane * LS_STRIDE + ((j)&1)*16);                            \
            s4[0] = make_float4(C[0], C[3], C[6], itx);                         \
            s4[1] = make_float4(C[1], C[4], C[7], ity);                         \
            s4[2] = make_float4(C[2], C[5], C[8], itz);                         \
            s4[3] = make_float4(0.f, 0.f, 0.f, 1.f);                            \
        }                                                                       \
    } while (0)

    // flush 2 staged joints (chunk c = 0..11): 32 floats/elem -> 8 float4 iters
#define FLUSH(c)                                                                \
    do {                                                                        \
        __syncwarp();                                                           \
        _Pragma("unroll")                                                       \
        for (int k = 0; k < 8; ++k) {                                           \
            int q = k * 32 + lane;                                              \
            int r = q >> 3;                                                     \
            int w = (q & 7) * 4;                                                \
            float4 a = *reinterpret_cast<float4*>(Lb + r * LS_STRIDE + w);      \
            float4 b = *reinterpret_cast<float4*>(Sb + r * LS_STRIDE + w);      \
            if (i0 + r < B) {                                                   \
                size_t base = (size_t)(i0 + r) * 384 + (c) * 32 + w;            \
                *reinterpret_cast<float4*>(l2wo + base)  = a;                   \
                *reinterpret_cast<float4*>(sktso + base) = b;                   \
            }                                                                   \
        }                                                                       \
        _Pragma("unroll")                                                       \
        for (int k = 0; k < 6; ++k) {                                           \
            int q = k * 32 + lane;                                              \
            int r = q / 6;                                                      \
            int m = q - r * 6;                                                  \
            if (i0 + r < B)                                                     \
                kpo[(size_t)(i0 + r) * 72 + (c) * 6 + m] = KP[r * 7 + m];       \
        }                                                                       \
        __syncwarp();                                                           \
    } while (0)

    // topological order; parent always computed before child
    BONES4(0);
    JOINT(0, 0);   JOINT(1, 0);   FLUSH(0);
    JOINT(2, 0);   JOINT(3, 0);   FLUSH(1);
    BONES4(4);
    JOINT(4, 1);   JOINT(5, 2);   FLUSH(2);
    JOINT(6, 3);   JOINT(7, 4);   FLUSH(3);
    BONES4(8);
    JOINT(8, 5);   JOINT(9, 6);   FLUSH(4);
    JOINT(10, 7);  JOINT(11, 8);  FLUSH(5);
    BONES4(12);
    JOINT(12, 9);  JOINT(13, 9);  FLUSH(6);
    JOINT(14, 9);  JOINT(15, 12); FLUSH(7);
    BONES4(16);
    JOINT(16, 13); JOINT(17, 14); FLUSH(8);
    JOINT(18, 16); JOINT(19, 17); FLUSH(9);
    BONES4(20);
    JOINT(20, 18); JOINT(21, 19); FLUSH(10);
    JOINT(22, 20); JOINT(23, 21); FLUSH(11);

#undef JOINT
#undef FLUSH
#undef BONES4
}

// ---------------------------------------------------------------------------
// Kernel 2: rots + bone copy  (one thread per (element, joint) pair;
// outputs staged in smem, flushed fully coalesced)
// ---------------------------------------------------------------------------
__global__ void __launch_bounds__(256)
rot_kernel(const float* __restrict__ bones, const int* __restrict__ idxs,
           float* __restrict__ out, int B)
{
    __shared__ float rt[256 * 9];
    __shared__ float bt[256 * 3];
    const int tid = threadIdx.x;
    const long long p0 = (long long)blockIdx.x * 256;
    const long long p  = p0 + tid;
    const long long NP = (long long)B * 24;

    int ii = (int)(p / 24);
    int jj = (int)(p - (long long)ii * 24);
    const bool act = (p < NP);
    const int idx = act ? idxs[ii] : 0;

    const float* bp = bones + (size_t)idx * 72 + jj * 3;
    float vx = __ldg(bp + 0), vy = __ldg(bp + 1), vz = __ldg(bp + 2);
    bt[tid * 3 + 0] = vx; bt[tid * 3 + 1] = vy; bt[tid * 3 + 2] = vz;

    float R[9];
    axisang_rot(vx, vy, vz, R);
#pragma unroll
    for (int m = 0; m < 9; ++m) rt[tid * 9 + m] = R[m];

    __syncthreads();

    float* rotso = out + (size_t)B * 912;
    float* boneo = out + (size_t)B * 72;

    const long long rbase = p0 * 9;
#pragma unroll
    for (int k = 0; k < 3; ++k) {
        int q = k * 256 + tid;
        if (q < 576) {
            long long g = rbase + (long long)q * 4;
            if (g < (long long)B * 216)
                *reinterpret_cast<float4*>(rotso + g) =
                    reinterpret_cast<float4*>(rt)[q];
        }
    }
    if (tid < 192) {
        long long g = p0 * 3 + (long long)tid * 4;
        if (g < (long long)B * 72)
            *reinterpret_cast<float4*>(boneo + g) =
                reinterpret_cast<float4*>(bt)[tid];
    }
}

extern "C" void kernel_launch(void* const* d_in, const int* in_sizes, int n_in,
                              void* d_out, int out_size)
{
    const float* pelvis = (const float*)d_in[0];
    const float* bones  = (const float*)d_in[1];
    const float* rest   = (const float*)d_in[2];
    const int*   idxs   = (const int*)d_in[3];
    const int B = in_sizes[3];
    float* out = (float*)d_out;

    const int smem1 = 4 * WARP_WORDS * 4;  // 40,448 bytes
    cudaFuncSetAttribute(chain_kernel,
                         cudaFuncAttributeMaxDynamicSharedMemorySize, smem1);

    int blocks1 = (B + 127) / 128;
    chain_kernel<<<blocks1, 128, smem1>>>(pelvis, bones, rest, idxs, out, B);

    long long pairs = (long long)B * 24;
    int blocks2 = (int)((pairs + 255) / 256);
    rot_kernel<<<blocks2, 256>>>(bones, idxs, out, B);
}